// round 1
// baseline (speedup 1.0000x reference)
#include <cuda_runtime.h>
#include <math.h>

#define H_SIZE 2048
#define INTER_SZ 8192
#define NQ 16
#define NKV 8
#define HD 128
#define SEQ 2048
#define BATCH 2
#define NROWS (BATCH*SEQ)
#define WIN 1024

// ---------------- scratch (module-scope device globals; no runtime alloc) ----------------
__device__ float g_h[NROWS*H_SIZE];
__device__ float g_q[NROWS*H_SIZE];
__device__ float g_k[NROWS*NKV*HD];
__device__ float g_v[NROWS*NKV*HD];
__device__ float g_attn[NROWS*H_SIZE];
__device__ float g_attnout[NROWS*H_SIZE];
__device__ float g_h2[NROWS*H_SIZE];
__device__ float g_ffnin[NROWS*H_SIZE];
__device__ float g_gate[NROWS*INTER_SZ];
__device__ float g_up[NROWS*INTER_SZ];
__device__ float g_ffnout[NROWS*H_SIZE];

// ---------------- RMSNorm (mode 0: norm; 1: res + norm; 2: (res + norm)*scalar) ----------
__global__ __launch_bounds__(256) void rmsnorm_kernel(
    const float* __restrict__ in, const float* __restrict__ w,
    const float* __restrict__ res, const float* __restrict__ scal,
    float* __restrict__ out, int mode)
{
    int row = blockIdx.x;
    int t = threadIdx.x;
    const float4* ip = (const float4*)(in + (size_t)row * H_SIZE);
    float4 v0 = ip[t];
    float4 v1 = ip[t + 256];
    float ss = v0.x*v0.x + v0.y*v0.y + v0.z*v0.z + v0.w*v0.w
             + v1.x*v1.x + v1.y*v1.y + v1.z*v1.z + v1.w*v1.w;
    #pragma unroll
    for (int o = 16; o; o >>= 1) ss += __shfl_xor_sync(0xffffffffu, ss, o);
    __shared__ float red[8];
    if ((t & 31) == 0) red[t >> 5] = ss;
    __syncthreads();
    float tot = red[0]+red[1]+red[2]+red[3]+red[4]+red[5]+red[6]+red[7];
    float inv = rsqrtf(tot * (1.0f / H_SIZE) + 1e-6f);

    const float4* w4 = (const float4*)w;
    float4 w0 = w4[t], w1 = w4[t + 256];
    float4 o0, o1;
    o0.x = v0.x*inv*w0.x; o0.y = v0.y*inv*w0.y; o0.z = v0.z*inv*w0.z; o0.w = v0.w*inv*w0.w;
    o1.x = v1.x*inv*w1.x; o1.y = v1.y*inv*w1.y; o1.z = v1.z*inv*w1.z; o1.w = v1.w*inv*w1.w;
    if (mode >= 1) {
        const float4* rp = (const float4*)(res + (size_t)row * H_SIZE);
        float4 r0 = rp[t], r1 = rp[t + 256];
        o0.x += r0.x; o0.y += r0.y; o0.z += r0.z; o0.w += r0.w;
        o1.x += r1.x; o1.y += r1.y; o1.z += r1.z; o1.w += r1.w;
    }
    if (mode == 2) {
        float sc = scal[0];
        o0.x *= sc; o0.y *= sc; o0.z *= sc; o0.w *= sc;
        o1.x *= sc; o1.y *= sc; o1.z *= sc; o1.w *= sc;
    }
    float4* op = (float4*)(out + (size_t)row * H_SIZE);
    op[t] = o0;
    op[t + 256] = o1;
}

// ---------------- GEMM: C[M,N] = A[M,K] * B[N,K]^T (all row-major) ----------------------
// 128x128 block, BK=8, 256 threads, 8x8 microtile with split (4+4) fragments.
__global__ __launch_bounds__(256) void gemm_abt(
    const float* __restrict__ A, const float* __restrict__ B,
    float* __restrict__ C, int M, int N, int K)
{
    __shared__ float As[8][128];
    __shared__ float Bs[8][128];
    int tid = threadIdx.x;
    int tx = tid & 15, ty = tid >> 4;
    int bx = blockIdx.x, by = blockIdx.y;
    const float* Ab = A + (size_t)by * 128 * K;
    const float* Bb = B + (size_t)bx * 128 * K;
    int lrow = tid >> 1;
    int lcol = (tid & 1) * 4;

    float acc[8][8];
    #pragma unroll
    for (int i = 0; i < 8; i++)
        #pragma unroll
        for (int j = 0; j < 8; j++) acc[i][j] = 0.f;

    for (int k0 = 0; k0 < K; k0 += 8) {
        float4 av = *(const float4*)(Ab + (size_t)lrow * K + k0 + lcol);
        float4 bv = *(const float4*)(Bb + (size_t)lrow * K + k0 + lcol);
        As[lcol + 0][lrow] = av.x; As[lcol + 1][lrow] = av.y;
        As[lcol + 2][lrow] = av.z; As[lcol + 3][lrow] = av.w;
        Bs[lcol + 0][lrow] = bv.x; Bs[lcol + 1][lrow] = bv.y;
        Bs[lcol + 2][lrow] = bv.z; Bs[lcol + 3][lrow] = bv.w;
        __syncthreads();
        #pragma unroll
        for (int kk = 0; kk < 8; kk++) {
            float4 a0 = *(const float4*)&As[kk][ty * 4];
            float4 a1 = *(const float4*)&As[kk][64 + ty * 4];
            float4 b0 = *(const float4*)&Bs[kk][tx * 4];
            float4 b1 = *(const float4*)&Bs[kk][64 + tx * 4];
            float a[8] = {a0.x, a0.y, a0.z, a0.w, a1.x, a1.y, a1.z, a1.w};
            float b[8] = {b0.x, b0.y, b0.z, b0.w, b1.x, b1.y, b1.z, b1.w};
            #pragma unroll
            for (int i = 0; i < 8; i++)
                #pragma unroll
                for (int j = 0; j < 8; j++)
                    acc[i][j] += a[i] * b[j];
        }
        __syncthreads();
    }

    #pragma unroll
    for (int i = 0; i < 8; i++) {
        int rm = (i < 4) ? (ty * 4 + i) : (64 + ty * 4 + (i - 4));
        float* Cr = C + (size_t)(by * 128 + rm) * N + bx * 128;
        float4 c0 = {acc[i][0], acc[i][1], acc[i][2], acc[i][3]};
        float4 c1 = {acc[i][4], acc[i][5], acc[i][6], acc[i][7]};
        *(float4*)(Cr + tx * 4) = c0;
        *(float4*)(Cr + 64 + tx * 4) = c1;
    }
}

// ---------------- RoPE (in-place on [NROWS, nheads*128]) --------------------------------
__global__ __launch_bounds__(256) void rope_kernel(float* __restrict__ buf, int nheads)
{
    int row = blockIdx.x;
    int s = row & (SEQ - 1);
    float* base = buf + (size_t)row * nheads * HD;
    for (int idx = threadIdx.x; idx < nheads * 64; idx += blockDim.x) {
        int hh = idx >> 6;
        int d = idx & 63;
        float inv = expf(-((float)d * (1.0f / 64.0f)) * 9.210340371976184f); // ln(10000)
        float fr = (float)s * inv;
        float sn = sinf(fr), cs = cosf(fr);
        float* p = base + hh * HD + d;
        float x1 = p[0], x2 = p[64];
        p[0]  = x1 * cs - x2 * sn;
        p[64] = x2 * cs + x1 * sn;
    }
}

// ---------------- Sliding-window GQA flash attention ------------------------------------
// grid (SEQ/64, NQ, BATCH), 256 threads; row r = tid>>2 owns query i0+r via 4 lanes c=tid&3.
// Lane c owns keys {c+4u} of each 32-key tile and dim chunks {4*(c+4t)..+3}.
#define QSTR 132
#define PSTR 36
#define ATTN_SMEM_FLOATS (64*QSTR + 32*QSTR + 32*QSTR + 64*PSTR)

__global__ __launch_bounds__(256) void attn_kernel(
    const float* __restrict__ Q, const float* __restrict__ K,
    const float* __restrict__ V, float* __restrict__ O)
{
    extern __shared__ float sm[];
    float* Qs = sm;
    float* Ks = sm + 64 * QSTR;
    float* Vs = Ks + 32 * QSTR;
    float* Ps = Vs + 32 * QSTR;

    const int i0 = blockIdx.x * 64;
    const int h  = blockIdx.y;
    const int b  = blockIdx.z;
    const int hk = h >> 1;
    const int tid = threadIdx.x;
    const int r = tid >> 2, c = tid & 3;
    const float scale = 0.08838834764831845f; // 1/sqrt(128)

    // load + pre-scale Q tile
    #pragma unroll
    for (int it = 0; it < 8; it++) {
        int idx = tid + 256 * it;
        int rr = idx >> 5, d4 = idx & 31;
        float4 qv = *(const float4*)(Q + ((size_t)(b * SEQ + i0 + rr) * H_SIZE + h * HD + d4 * 4));
        float4 qs = {qv.x * scale, qv.y * scale, qv.z * scale, qv.w * scale};
        *(float4*)&Qs[rr * QSTR + d4 * 4] = qs;
    }

    float m = -1e30f, l = 0.f;
    float4 o[8];
    #pragma unroll
    for (int t8 = 0; t8 < 8; t8++) o[t8] = make_float4(0.f, 0.f, 0.f, 0.f);

    int jstart = i0 - (WIN - 1);
    if (jstart < 0) jstart = 0;
    jstart &= ~31;
    const int iq = i0 + r;
    const float* qrow = Qs + r * QSTR;

    for (int j0 = jstart; j0 < i0 + 64; j0 += 32) {
        __syncthreads();
        #pragma unroll
        for (int it = 0; it < 4; it++) {
            int idx = tid + 256 * it;
            int rr = idx >> 5, d4 = idx & 31;
            size_t goff = (size_t)(b * SEQ + j0 + rr) * (NKV * HD) + hk * HD + d4 * 4;
            *(float4*)&Ks[rr * QSTR + d4 * 4] = *(const float4*)(K + goff);
            *(float4*)&Vs[rr * QSTR + d4 * 4] = *(const float4*)(V + goff);
        }
        __syncthreads();

        float s[8];
        #pragma unroll
        for (int u = 0; u < 8; u++) s[u] = 0.f;
        #pragma unroll 4
        for (int d4 = 0; d4 < 32; d4++) {
            float4 qv = *(const float4*)(qrow + d4 * 4);
            #pragma unroll
            for (int u = 0; u < 8; u++) {
                float4 kv = *(const float4*)&Ks[(c + 4 * u) * QSTR + d4 * 4];
                s[u] += qv.x * kv.x + qv.y * kv.y + qv.z * kv.z + qv.w * kv.w;
            }
        }

        float mt = m;
        #pragma unroll
        for (int u = 0; u < 8; u++) {
            int j = j0 + c + 4 * u;
            bool ok = (j <= iq) && (iq - j < WIN);
            s[u] = ok ? s[u] : -1e30f;
            mt = fmaxf(mt, s[u]);
        }
        mt = fmaxf(mt, __shfl_xor_sync(0xffffffffu, mt, 1));
        mt = fmaxf(mt, __shfl_xor_sync(0xffffffffu, mt, 2));
        float alpha = __expf(m - mt);
        m = mt;
        float psum = 0.f;
        #pragma unroll
        for (int u = 0; u < 8; u++) {
            float p = __expf(s[u] - mt);
            psum += p;
            Ps[r * PSTR + c + 4 * u] = p;
        }
        l = l * alpha + psum;
        #pragma unroll
        for (int t8 = 0; t8 < 8; t8++) {
            o[t8].x *= alpha; o[t8].y *= alpha; o[t8].z *= alpha; o[t8].w *= alpha;
        }
        __syncwarp();
        #pragma unroll 4
        for (int jj = 0; jj < 32; jj++) {
            float pj = Ps[r * PSTR + jj];
            #pragma unroll
            for (int t8 = 0; t8 < 8; t8++) {
                float4 vv = *(const float4*)&Vs[jj * QSTR + (c + 4 * t8) * 4];
                o[t8].x += pj * vv.x; o[t8].y += pj * vv.y;
                o[t8].z += pj * vv.z; o[t8].w += pj * vv.w;
            }
        }
        __syncwarp();
    }

    l += __shfl_xor_sync(0xffffffffu, l, 1);
    l += __shfl_xor_sync(0xffffffffu, l, 2);
    float linv = 1.0f / l;
    float* orow = O + (size_t)(b * SEQ + i0 + r) * H_SIZE + h * HD;
    #pragma unroll
    for (int t8 = 0; t8 < 8; t8++) {
        float4 ov = {o[t8].x * linv, o[t8].y * linv, o[t8].z * linv, o[t8].w * linv};
        *(float4*)(orow + (c + 4 * t8) * 4) = ov;
    }
}

// ---------------- GeGLU elementwise: o = gelu_exact(g) * u -------------------------------
__device__ __forceinline__ float gelu_exact(float x) {
    return 0.5f * x * (1.0f + erff(x * 0.7071067811865476f));
}
__global__ __launch_bounds__(256) void geglu_kernel(
    const float* __restrict__ g, const float* __restrict__ u,
    float* __restrict__ o, int n4)
{
    int i = blockIdx.x * blockDim.x + threadIdx.x;
    int stride = gridDim.x * blockDim.x;
    for (; i < n4; i += stride) {
        float4 gv = ((const float4*)g)[i];
        float4 uv = ((const float4*)u)[i];
        float4 r;
        r.x = gelu_exact(gv.x) * uv.x;
        r.y = gelu_exact(gv.y) * uv.y;
        r.z = gelu_exact(gv.z) * uv.z;
        r.w = gelu_exact(gv.w) * uv.w;
        ((float4*)o)[i] = r;
    }
}

// ---------------- launch ----------------------------------------------------------------
extern "C" void kernel_launch(void* const* d_in, const int* in_sizes, int n_in,
                              void* d_out, int out_size)
{
    const float* x    = (const float*)d_in[0];
    const float* wq   = (const float*)d_in[1];
    const float* wk   = (const float*)d_in[2];
    const float* wv   = (const float*)d_in[3];
    const float* wo   = (const float*)d_in[4];
    const float* w_in = (const float*)d_in[5];
    const float* w_pa = (const float*)d_in[6];
    const float* w_pf = (const float*)d_in[7];
    const float* w_pff= (const float*)d_in[8];
    const float* wg   = (const float*)d_in[9];
    const float* wu   = (const float*)d_in[10];
    const float* wd   = (const float*)d_in[11];
    const float* lsc  = (const float*)d_in[12];
    float* out = (float*)d_out;

    float *h, *q, *k, *v, *attn, *attnout, *h2, *ffnin, *gate, *up, *ffnout;
    cudaGetSymbolAddress((void**)&h,       g_h);
    cudaGetSymbolAddress((void**)&q,       g_q);
    cudaGetSymbolAddress((void**)&k,       g_k);
    cudaGetSymbolAddress((void**)&v,       g_v);
    cudaGetSymbolAddress((void**)&attn,    g_attn);
    cudaGetSymbolAddress((void**)&attnout, g_attnout);
    cudaGetSymbolAddress((void**)&h2,      g_h2);
    cudaGetSymbolAddress((void**)&ffnin,   g_ffnin);
    cudaGetSymbolAddress((void**)&gate,    g_gate);
    cudaGetSymbolAddress((void**)&up,      g_up);
    cudaGetSymbolAddress((void**)&ffnout,  g_ffnout);

    const int attn_smem = ATTN_SMEM_FLOATS * (int)sizeof(float);
    cudaFuncSetAttribute(attn_kernel, cudaFuncAttributeMaxDynamicSharedMemorySize, attn_smem);

    // h = rmsnorm(x, w_in)
    rmsnorm_kernel<<<NROWS, 256>>>(x, w_in, nullptr, nullptr, h, 0);
    // QKV
    gemm_abt<<<dim3(H_SIZE/128, NROWS/128), 256>>>(h, wq, q, NROWS, H_SIZE, H_SIZE);
    gemm_abt<<<dim3((NKV*HD)/128, NROWS/128), 256>>>(h, wk, k, NROWS, NKV*HD, H_SIZE);
    gemm_abt<<<dim3((NKV*HD)/128, NROWS/128), 256>>>(h, wv, v, NROWS, NKV*HD, H_SIZE);
    // RoPE
    rope_kernel<<<NROWS, 256>>>(q, NQ);
    rope_kernel<<<NROWS, 256>>>(k, NKV);
    // attention
    attn_kernel<<<dim3(SEQ/64, NQ, BATCH), 256, attn_smem>>>(q, k, v, attn);
    // WO
    gemm_abt<<<dim3(H_SIZE/128, NROWS/128), 256>>>(attn, wo, attnout, NROWS, H_SIZE, H_SIZE);
    // h2 = x + rmsnorm(attnout, w_pa)
    rmsnorm_kernel<<<NROWS, 256>>>(attnout, w_pa, x, nullptr, h2, 1);
    // ffn_in = rmsnorm(h2, w_pf)
    rmsnorm_kernel<<<NROWS, 256>>>(h2, w_pf, nullptr, nullptr, ffnin, 0);
    // gate/up GEMMs
    gemm_abt<<<dim3(INTER_SZ/128, NROWS/128), 256>>>(ffnin, wg, gate, NROWS, INTER_SZ, H_SIZE);
    gemm_abt<<<dim3(INTER_SZ/128, NROWS/128), 256>>>(ffnin, wu, up, NROWS, INTER_SZ, H_SIZE);
    // act = gelu(gate) * up   (into gate)
    geglu_kernel<<<8192, 256>>>(gate, up, gate, (NROWS * INTER_SZ) / 4);
    // down projection
    gemm_abt<<<dim3(H_SIZE/128, NROWS/128), 256>>>(gate, wd, ffnout, NROWS, H_SIZE, INTER_SZ);
    // out = (h2 + rmsnorm(ffnout, w_pff)) * layer_scalar
    rmsnorm_kernel<<<NROWS, 256>>>(ffnout, w_pff, h2, lsc, out, 2);
}

// round 3
// speedup vs baseline: 2.1707x; 2.1707x over previous
#include <cuda_runtime.h>
#include <cuda_bf16.h>
#include <stdint.h>
#include <math.h>

#define H_SIZE 2048
#define INTER_SZ 8192
#define NQ 16
#define NKV 8
#define HD 128
#define SEQ 2048
#define BATCH 2
#define NROWS (BATCH*SEQ)
#define WIN 1024

// ---------------- scratch (module-scope device globals; no runtime alloc) ----------------
__device__ float g_h[NROWS*H_SIZE];
__device__ float g_q[NROWS*H_SIZE];
__device__ float g_k[NROWS*NKV*HD];
__device__ float g_v[NROWS*NKV*HD];
__device__ float g_attn[NROWS*H_SIZE];
__device__ float g_attnout[NROWS*H_SIZE];
__device__ float g_h2[NROWS*H_SIZE];
__device__ float g_ffnin[NROWS*H_SIZE];
__device__ float g_gate[NROWS*INTER_SZ];
__device__ float g_up[NROWS*INTER_SZ];
__device__ float g_ffnout[NROWS*H_SIZE];

// ---------------- RMSNorm (mode 0: norm; 1: res + norm; 2: (res + norm)*scalar) ----------
__global__ __launch_bounds__(256) void rmsnorm_kernel(
    const float* __restrict__ in, const float* __restrict__ w,
    const float* __restrict__ res, const float* __restrict__ scal,
    float* __restrict__ out, int mode)
{
    int row = blockIdx.x;
    int t = threadIdx.x;
    const float4* ip = (const float4*)(in + (size_t)row * H_SIZE);
    float4 v0 = ip[t];
    float4 v1 = ip[t + 256];
    float ss = v0.x*v0.x + v0.y*v0.y + v0.z*v0.z + v0.w*v0.w
             + v1.x*v1.x + v1.y*v1.y + v1.z*v1.z + v1.w*v1.w;
    #pragma unroll
    for (int o = 16; o; o >>= 1) ss += __shfl_xor_sync(0xffffffffu, ss, o);
    __shared__ float red[8];
    if ((t & 31) == 0) red[t >> 5] = ss;
    __syncthreads();
    float tot = red[0]+red[1]+red[2]+red[3]+red[4]+red[5]+red[6]+red[7];
    float inv = rsqrtf(tot * (1.0f / H_SIZE) + 1e-6f);

    const float4* w4 = (const float4*)w;
    float4 w0 = w4[t], w1 = w4[t + 256];
    float4 o0, o1;
    o0.x = v0.x*inv*w0.x; o0.y = v0.y*inv*w0.y; o0.z = v0.z*inv*w0.z; o0.w = v0.w*inv*w0.w;
    o1.x = v1.x*inv*w1.x; o1.y = v1.y*inv*w1.y; o1.z = v1.z*inv*w1.z; o1.w = v1.w*inv*w1.w;
    if (mode >= 1) {
        const float4* rp = (const float4*)(res + (size_t)row * H_SIZE);
        float4 r0 = rp[t], r1 = rp[t + 256];
        o0.x += r0.x; o0.y += r0.y; o0.z += r0.z; o0.w += r0.w;
        o1.x += r1.x; o1.y += r1.y; o1.z += r1.z; o1.w += r1.w;
    }
    if (mode == 2) {
        float sc = scal[0];
        o0.x *= sc; o0.y *= sc; o0.z *= sc; o0.w *= sc;
        o1.x *= sc; o1.y *= sc; o1.z *= sc; o1.w *= sc;
    }
    float4* op = (float4*)(out + (size_t)row * H_SIZE);
    op[t] = o0;
    op[t + 256] = o1;
}

// ---------------- Tensor-core GEMM: C[M,N] = A[M,K] * B[N,K]^T  (bf16x3 split) -----------
// 128x128 block, BK=32, 256 threads = 8 warps in 2(m) x 4(n), warp tile 64x32.
// mma.m16n8k16.bf16: fp32 inputs split into bf16 hi/lo; acc += Ah*Bh + Ah*Bl + Al*Bh.

#define LDSK 40   // padded row stride in halfs

__device__ __forceinline__ void mma_bf16(float* c, const uint32_t* a, const uint32_t* b) {
    asm volatile(
        "mma.sync.aligned.m16n8k16.row.col.f32.bf16.bf16.f32 "
        "{%0,%1,%2,%3}, {%4,%5,%6,%7}, {%8,%9}, {%0,%1,%2,%3};\n"
        : "+f"(c[0]), "+f"(c[1]), "+f"(c[2]), "+f"(c[3])
        : "r"(a[0]), "r"(a[1]), "r"(a[2]), "r"(a[3]), "r"(b[0]), "r"(b[1]));
}

__device__ __forceinline__ void cvt_store(__nv_bfloat16* sh, __nv_bfloat16* sl, float4 v) {
    __nv_bfloat16 hx = __float2bfloat16(v.x);
    __nv_bfloat16 hy = __float2bfloat16(v.y);
    __nv_bfloat16 hz = __float2bfloat16(v.z);
    __nv_bfloat16 hw = __float2bfloat16(v.w);
    __nv_bfloat16 lx = __float2bfloat16(v.x - __bfloat162float(hx));
    __nv_bfloat16 ly = __float2bfloat16(v.y - __bfloat162float(hy));
    __nv_bfloat16 lz = __float2bfloat16(v.z - __bfloat162float(hz));
    __nv_bfloat16 lw = __float2bfloat16(v.w - __bfloat162float(hw));
    *(__nv_bfloat162*)(sh)     = __halves2bfloat162(hx, hy);
    *(__nv_bfloat162*)(sh + 2) = __halves2bfloat162(hz, hw);
    *(__nv_bfloat162*)(sl)     = __halves2bfloat162(lx, ly);
    *(__nv_bfloat162*)(sl + 2) = __halves2bfloat162(lz, lw);
}

__global__ __launch_bounds__(256) void gemm_mma(
    const float* __restrict__ A, const float* __restrict__ B,
    float* __restrict__ C, int M, int N, int K)
{
    __shared__ __align__(16) __nv_bfloat16 Ahs[128*LDSK];
    __shared__ __align__(16) __nv_bfloat16 Als[128*LDSK];
    __shared__ __align__(16) __nv_bfloat16 Bhs[128*LDSK];
    __shared__ __align__(16) __nv_bfloat16 Bls[128*LDSK];

    const int tid  = threadIdx.x;
    const int warp = tid >> 5, lane = tid & 31;
    const int wm = warp >> 2, wn = warp & 3;   // 2 x 4 warp grid
    const int g = lane >> 2, t = lane & 3;

    const float* Ab = A + (size_t)blockIdx.y * 128 * K;
    const float* Bb = B + (size_t)blockIdx.x * 128 * K;

    const int lrow = tid >> 3;        // 0..31
    const int lcol = (tid & 7) * 4;   // 0..28

    float acc[4][4][4];
    #pragma unroll
    for (int i = 0; i < 4; i++)
        #pragma unroll
        for (int j = 0; j < 4; j++)
            #pragma unroll
            for (int q = 0; q < 4; q++) acc[i][j][q] = 0.f;

    float4 pa[4], pb[4];
    #pragma unroll
    for (int i = 0; i < 4; i++) {
        pa[i] = *(const float4*)(Ab + (size_t)(lrow + 32*i) * K + lcol);
        pb[i] = *(const float4*)(Bb + (size_t)(lrow + 32*i) * K + lcol);
    }

    for (int k0 = 0; k0 < K; k0 += 32) {
        #pragma unroll
        for (int i = 0; i < 4; i++) {
            int off = (lrow + 32*i) * LDSK + lcol;
            cvt_store(Ahs + off, Als + off, pa[i]);
            cvt_store(Bhs + off, Bls + off, pb[i]);
        }
        __syncthreads();
        if (k0 + 32 < K) {
            #pragma unroll
            for (int i = 0; i < 4; i++) {
                pa[i] = *(const float4*)(Ab + (size_t)(lrow + 32*i) * K + (k0 + 32) + lcol);
                pb[i] = *(const float4*)(Bb + (size_t)(lrow + 32*i) * K + (k0 + 32) + lcol);
            }
        }
        #pragma unroll
        for (int kk = 0; kk < 32; kk += 16) {
            uint32_t fa[4][4], fb[4][2];
            #pragma unroll
            for (int tm = 0; tm < 4; tm++) {
                int r0 = (wm*64 + tm*16 + g) * LDSK + kk + 2*t;
                int r1 = r0 + 8*LDSK;
                fa[tm][0] = *(const uint32_t*)(Ahs + r0);
                fa[tm][1] = *(const uint32_t*)(Ahs + r1);
                fa[tm][2] = *(const uint32_t*)(Ahs + r0 + 8);
                fa[tm][3] = *(const uint32_t*)(Ahs + r1 + 8);
            }
            #pragma unroll
            for (int tn = 0; tn < 4; tn++) {
                int r = (wn*32 + tn*8 + g) * LDSK + kk + 2*t;
                fb[tn][0] = *(const uint32_t*)(Bhs + r);
                fb[tn][1] = *(const uint32_t*)(Bhs + r + 8);
            }
            // pass 1: Ah * Bh
            #pragma unroll
            for (int tm = 0; tm < 4; tm++)
                #pragma unroll
                for (int tn = 0; tn < 4; tn++)
                    mma_bf16(acc[tm][tn], fa[tm], fb[tn]);
            // pass 2: Ah * Bl
            {
                uint32_t fbl[4][2];
                #pragma unroll
                for (int tn = 0; tn < 4; tn++) {
                    int r = (wn*32 + tn*8 + g) * LDSK + kk + 2*t;
                    fbl[tn][0] = *(const uint32_t*)(Bls + r);
                    fbl[tn][1] = *(const uint32_t*)(Bls + r + 8);
                }
                #pragma unroll
                for (int tm = 0; tm < 4; tm++)
                    #pragma unroll
                    for (int tn = 0; tn < 4; tn++)
                        mma_bf16(acc[tm][tn], fa[tm], fbl[tn]);
            }
            // pass 3: Al * Bh
            {
                uint32_t fal[4][4];
                #pragma unroll
                for (int tm = 0; tm < 4; tm++) {
                    int r0 = (wm*64 + tm*16 + g) * LDSK + kk + 2*t;
                    int r1 = r0 + 8*LDSK;
                    fal[tm][0] = *(const uint32_t*)(Als + r0);
                    fal[tm][1] = *(const uint32_t*)(Als + r1);
                    fal[tm][2] = *(const uint32_t*)(Als + r0 + 8);
                    fal[tm][3] = *(const uint32_t*)(Als + r1 + 8);
                }
                #pragma unroll
                for (int tm = 0; tm < 4; tm++)
                    #pragma unroll
                    for (int tn = 0; tn < 4; tn++)
                        mma_bf16(acc[tm][tn], fal[tm], fb[tn]);
            }
        }
        __syncthreads();
    }

    #pragma unroll
    for (int tm = 0; tm < 4; tm++) {
        #pragma unroll
        for (int tn = 0; tn < 4; tn++) {
            int row = blockIdx.y*128 + wm*64 + tm*16 + g;
            int col = blockIdx.x*128 + wn*32 + tn*8 + 2*t;
            float2 c0 = {acc[tm][tn][0], acc[tm][tn][1]};
            float2 c1 = {acc[tm][tn][2], acc[tm][tn][3]};
            *(float2*)(C + (size_t)row * N + col)       = c0;
            *(float2*)(C + (size_t)(row + 8) * N + col) = c1;
        }
    }
}

// ---------------- RoPE (in-place on [NROWS, nheads*128]) --------------------------------
__global__ __launch_bounds__(256) void rope_kernel(float* __restrict__ buf, int nheads)
{
    int row = blockIdx.x;
    int s = row & (SEQ - 1);
    float* base = buf + (size_t)row * nheads * HD;
    for (int idx = threadIdx.x; idx < nheads * 64; idx += blockDim.x) {
        int hh = idx >> 6;
        int d = idx & 63;
        float inv = expf(-((float)d * (1.0f / 64.0f)) * 9.210340371976184f); // ln(10000)
        float fr = (float)s * inv;
        float sn = sinf(fr), cs = cosf(fr);
        float* p = base + hh * HD + d;
        float x1 = p[0], x2 = p[64];
        p[0]  = x1 * cs - x2 * sn;
        p[64] = x2 * cs + x1 * sn;
    }
}

// ---------------- Sliding-window GQA flash attention ------------------------------------
#define QSTR 132
#define PSTR 36
#define ATTN_SMEM_FLOATS (64*QSTR + 32*QSTR + 32*QSTR + 64*PSTR)

__global__ __launch_bounds__(256) void attn_kernel(
    const float* __restrict__ Q, const float* __restrict__ K,
    const float* __restrict__ V, float* __restrict__ O)
{
    extern __shared__ float sm[];
    float* Qs = sm;
    float* Ks = sm + 64 * QSTR;
    float* Vs = Ks + 32 * QSTR;
    float* Ps = Vs + 32 * QSTR;

    const int i0 = blockIdx.x * 64;
    const int h  = blockIdx.y;
    const int b  = blockIdx.z;
    const int hk = h >> 1;
    const int tid = threadIdx.x;
    const int r = tid >> 2, c = tid & 3;
    const float scale = 0.08838834764831845f; // 1/sqrt(128)

    #pragma unroll
    for (int it = 0; it < 8; it++) {
        int idx = tid + 256 * it;
        int rr = idx >> 5, d4 = idx & 31;
        float4 qv = *(const float4*)(Q + ((size_t)(b * SEQ + i0 + rr) * H_SIZE + h * HD + d4 * 4));
        float4 qs = {qv.x * scale, qv.y * scale, qv.z * scale, qv.w * scale};
        *(float4*)&Qs[rr * QSTR + d4 * 4] = qs;
    }

    float m = -1e30f, l = 0.f;
    float4 o[8];
    #pragma unroll
    for (int t8 = 0; t8 < 8; t8++) o[t8] = make_float4(0.f, 0.f, 0.f, 0.f);

    int jstart = i0 - (WIN - 1);
    if (jstart < 0) jstart = 0;
    jstart &= ~31;
    const int iq = i0 + r;
    const float* qrow = Qs + r * QSTR;

    for (int j0 = jstart; j0 < i0 + 64; j0 += 32) {
        __syncthreads();
        #pragma unroll
        for (int it = 0; it < 4; it++) {
            int idx = tid + 256 * it;
            int rr = idx >> 5, d4 = idx & 31;
            size_t goff = (size_t)(b * SEQ + j0 + rr) * (NKV * HD) + hk * HD + d4 * 4;
            *(float4*)&Ks[rr * QSTR + d4 * 4] = *(const float4*)(K + goff);
            *(float4*)&Vs[rr * QSTR + d4 * 4] = *(const float4*)(V + goff);
        }
        __syncthreads();

        float s[8];
        #pragma unroll
        for (int u = 0; u < 8; u++) s[u] = 0.f;
        #pragma unroll 4
        for (int d4 = 0; d4 < 32; d4++) {
            float4 qv = *(const float4*)(qrow + d4 * 4);
            #pragma unroll
            for (int u = 0; u < 8; u++) {
                float4 kv = *(const float4*)&Ks[(c + 4 * u) * QSTR + d4 * 4];
                s[u] += qv.x * kv.x + qv.y * kv.y + qv.z * kv.z + qv.w * kv.w;
            }
        }

        float mt = m;
        #pragma unroll
        for (int u = 0; u < 8; u++) {
            int j = j0 + c + 4 * u;
            bool ok = (j <= iq) && (iq - j < WIN);
            s[u] = ok ? s[u] : -1e30f;
            mt = fmaxf(mt, s[u]);
        }
        mt = fmaxf(mt, __shfl_xor_sync(0xffffffffu, mt, 1));
        mt = fmaxf(mt, __shfl_xor_sync(0xffffffffu, mt, 2));
        float alpha = __expf(m - mt);
        m = mt;
        float psum = 0.f;
        #pragma unroll
        for (int u = 0; u < 8; u++) {
            float p = __expf(s[u] - mt);
            psum += p;
            Ps[r * PSTR + c + 4 * u] = p;
        }
        l = l * alpha + psum;
        #pragma unroll
        for (int t8 = 0; t8 < 8; t8++) {
            o[t8].x *= alpha; o[t8].y *= alpha; o[t8].z *= alpha; o[t8].w *= alpha;
        }
        __syncwarp();
        #pragma unroll 4
        for (int jj = 0; jj < 32; jj++) {
            float pj = Ps[r * PSTR + jj];
            #pragma unroll
            for (int t8 = 0; t8 < 8; t8++) {
                float4 vv = *(const float4*)&Vs[jj * QSTR + (c + 4 * t8) * 4];
                o[t8].x += pj * vv.x; o[t8].y += pj * vv.y;
                o[t8].z += pj * vv.z; o[t8].w += pj * vv.w;
            }
        }
        __syncwarp();
    }

    l += __shfl_xor_sync(0xffffffffu, l, 1);
    l += __shfl_xor_sync(0xffffffffu, l, 2);
    float linv = 1.0f / l;
    float* orow = O + (size_t)(b * SEQ + i0 + r) * H_SIZE + h * HD;
    #pragma unroll
    for (int t8 = 0; t8 < 8; t8++) {
        float4 ov = {o[t8].x * linv, o[t8].y * linv, o[t8].z * linv, o[t8].w * linv};
        *(float4*)(orow + (c + 4 * t8) * 4) = ov;
    }
}

// ---------------- GeGLU elementwise: o = gelu_exact(g) * u -------------------------------
__device__ __forceinline__ float gelu_exact(float x) {
    return 0.5f * x * (1.0f + erff(x * 0.7071067811865476f));
}
__global__ __launch_bounds__(256) void geglu_kernel(
    const float* __restrict__ g, const float* __restrict__ u,
    float* __restrict__ o, int n4)
{
    int i = blockIdx.x * blockDim.x + threadIdx.x;
    int stride = gridDim.x * blockDim.x;
    for (; i < n4; i += stride) {
        float4 gv = ((const float4*)g)[i];
        float4 uv = ((const float4*)u)[i];
        float4 r;
        r.x = gelu_exact(gv.x) * uv.x;
        r.y = gelu_exact(gv.y) * uv.y;
        r.z = gelu_exact(gv.z) * uv.z;
        r.w = gelu_exact(gv.w) * uv.w;
        ((float4*)o)[i] = r;
    }
}

// ---------------- launch ----------------------------------------------------------------
extern "C" void kernel_launch(void* const* d_in, const int* in_sizes, int n_in,
                              void* d_out, int out_size)
{
    const float* x    = (const float*)d_in[0];
    const float* wq   = (const float*)d_in[1];
    const float* wk   = (const float*)d_in[2];
    const float* wv   = (const float*)d_in[3];
    const float* wo   = (const float*)d_in[4];
    const float* w_in = (const float*)d_in[5];
    const float* w_pa = (const float*)d_in[6];
    const float* w_pf = (const float*)d_in[7];
    const float* w_pff= (const float*)d_in[8];
    const float* wg   = (const float*)d_in[9];
    const float* wu   = (const float*)d_in[10];
    const float* wd   = (const float*)d_in[11];
    const float* lsc  = (const float*)d_in[12];
    float* out = (float*)d_out;

    float *h, *q, *k, *v, *attn, *attnout, *h2, *ffnin, *gate, *up, *ffnout;
    cudaGetSymbolAddress((void**)&h,       g_h);
    cudaGetSymbolAddress((void**)&q,       g_q);
    cudaGetSymbolAddress((void**)&k,       g_k);
    cudaGetSymbolAddress((void**)&v,       g_v);
    cudaGetSymbolAddress((void**)&attn,    g_attn);
    cudaGetSymbolAddress((void**)&attnout, g_attnout);
    cudaGetSymbolAddress((void**)&h2,      g_h2);
    cudaGetSymbolAddress((void**)&ffnin,   g_ffnin);
    cudaGetSymbolAddress((void**)&gate,    g_gate);
    cudaGetSymbolAddress((void**)&up,      g_up);
    cudaGetSymbolAddress((void**)&ffnout,  g_ffnout);

    const int attn_smem = ATTN_SMEM_FLOATS * (int)sizeof(float);
    cudaFuncSetAttribute(attn_kernel, cudaFuncAttributeMaxDynamicSharedMemorySize, attn_smem);

    // h = rmsnorm(x, w_in)
    rmsnorm_kernel<<<NROWS, 256>>>(x, w_in, nullptr, nullptr, h, 0);
    // QKV
    gemm_mma<<<dim3(H_SIZE/128, NROWS/128), 256>>>(h, wq, q, NROWS, H_SIZE, H_SIZE);
    gemm_mma<<<dim3((NKV*HD)/128, NROWS/128), 256>>>(h, wk, k, NROWS, NKV*HD, H_SIZE);
    gemm_mma<<<dim3((NKV*HD)/128, NROWS/128), 256>>>(h, wv, v, NROWS, NKV*HD, H_SIZE);
    // RoPE
    rope_kernel<<<NROWS, 256>>>(q, NQ);
    rope_kernel<<<NROWS, 256>>>(k, NKV);
    // attention
    attn_kernel<<<dim3(SEQ/64, NQ, BATCH), 256, attn_smem>>>(q, k, v, attn);
    // WO
    gemm_mma<<<dim3(H_SIZE/128, NROWS/128), 256>>>(attn, wo, attnout, NROWS, H_SIZE, H_SIZE);
    // h2 = x + rmsnorm(attnout, w_pa)
    rmsnorm_kernel<<<NROWS, 256>>>(attnout, w_pa, x, nullptr, h2, 1);
    // ffn_in = rmsnorm(h2, w_pf)
    rmsnorm_kernel<<<NROWS, 256>>>(h2, w_pf, nullptr, nullptr, ffnin, 0);
    // gate/up GEMMs
    gemm_mma<<<dim3(INTER_SZ/128, NROWS/128), 256>>>(ffnin, wg, gate, NROWS, INTER_SZ, H_SIZE);
    gemm_mma<<<dim3(INTER_SZ/128, NROWS/128), 256>>>(ffnin, wu, up, NROWS, INTER_SZ, H_SIZE);
    // act = gelu(gate) * up   (into gate)
    geglu_kernel<<<8192, 256>>>(gate, up, gate, (NROWS * INTER_SZ) / 4);
    // down projection
    gemm_mma<<<dim3(H_SIZE/128, NROWS/128), 256>>>(gate, wd, ffnout, NROWS, H_SIZE, INTER_SZ);
    // out = (h2 + rmsnorm(ffnout, w_pff)) * layer_scalar
    rmsnorm_kernel<<<NROWS, 256>>>(ffnout, w_pff, h2, lsc, out, 2);
}